// round 7
// baseline (speedup 1.0000x reference)
#include <cuda_runtime.h>
#include <cstdint>

// DiscreteAutoregressiveFlow: exact one-hot algebra over Z_257.
// next = (x_t * m[p] + c[p]) mod 257, per-state (m,c) from argmax of W[p]+b.
// Round 7: TWO launches. k_A = tables + x-extract + zero-fill (mixed R/W
// streams, 8 x uint4 per thread). k_BC = segmap fused with per-batch
// last-block stitch/replay/scatter (threadfence + atomic counter).

#define V       257
#define B       64
#define L       1024
#define SEG     32
#define SEGLEN  32
#define UNITS   8            // segments per segmap block -> 4 blocks per batch
#define REP     32           // table replication (bank == lane)
#define NST     258          // states 0..256 plus 257 = ZERO
#define TOTAL4  ((B * L * V) / 4)        // 4,214,784 uint4
#define TBLK    33                       // table blocks (264 warps >= 258)
#define MIXB    (TOTAL4 / 2048)          // 2058 blocks per role (exact)
#define SEGBLK  ((SEG / UNITS) * B)      // 256 segmap blocks

// Scratch (device globals; no allocation allowed).
__device__ unsigned g_tab[NST];                          // m | c<<16; 0 => dead
__device__ __align__(16) int   g_xidx[B * L];
__device__ __align__(16) short g_segmap[B * SEG * NST];
__device__ int g_done[B];                                // zero-init; self-resetting

// ---------------------------------------------------------------------------
// Doubled-table convention: slots 0..512 alias state (slot mod 257); slot 513
// = ZERO. step: z = x*m + c <= 65792; z mod 257 == (z&255) - (z>>8) (mod 257);
// w = lo - hi + 257 in [0,512] -> direct slot. Dead entry (e==0) -> slot 513.
// ---------------------------------------------------------------------------
__device__ __forceinline__ int slot_state(int slot) {
    return (slot == 513) ? V : ((slot >= V) ? slot - V : slot);
}
__device__ __forceinline__ int slot_src(int i) {        // slot -> g_tab index
    return (i < V) ? i : ((i == 513) ? V : i - V);
}

// ---------------------------------------------------------------------------
// K_A: three block roles in one launch; read stream (extract) and write
// stream (zero-fill) share the HBM pipe. 8 x uint4 per thread (MLP 8).
// ---------------------------------------------------------------------------
__global__ void __launch_bounds__(256) k_A(const float* __restrict__ W,
                                           const float* __restrict__ bb,
                                           const int*   __restrict__ inv_table,
                                           const uint4* __restrict__ x,
                                           uint4*       __restrict__ out) {
    int bid = blockIdx.x;
    int tid = threadIdx.x;

    if (bid < TBLK) {
        int p    = bid * 8 + (tid >> 5);
        int lane = tid & 31;
        if (p >= NST) return;
        const float* wrow = (p < V) ? (W + (size_t)p * (2 * V)) : nullptr;
        int bestj[2];
        #pragma unroll
        for (int h = 0; h < 2; h++) {
            float bv = -3.402823466e38f;
            int   bj = 0;
            for (int j = lane; j < V; j += 32) {
                int   col = h * V + j;
                float v   = bb[col] + (wrow ? wrow[col] : 0.0f);
                if (v > bv) { bv = v; bj = j; }     // first-max == jnp.argmax
            }
            #pragma unroll
            for (int off = 16; off; off >>= 1) {
                float ov = __shfl_down_sync(0xffffffffu, bv, off);
                int   oj = __shfl_down_sync(0xffffffffu, bj, off);
                if (ov > bv || (ov == bv && oj < bj)) { bv = ov; bj = oj; }
            }
            bestj[h] = bj;
        }
        if (lane == 0) {
            int l = bestj[0], s = bestj[1];
            int m = inv_table[s];                 // 0 iff s==0
            unsigned e = 0u;
            if (m != 0) {
                int c = (V - (l * m) % V) % V;
                e = (unsigned)m | ((unsigned)c << 16);
            }
            g_tab[p] = e;
        }
        return;
    }

    int m    = bid - TBLK;
    int unit = m >> 1;
    int base = unit * 2048 + tid;

    if (m & 1) {
        // zero-fill: 8 coalesced uint4 stores
        uint4 z = make_uint4(0u, 0u, 0u, 0u);
        #pragma unroll
        for (int k = 0; k < 8; k++) out[base + k * 256] = z;
        return;
    }

    // extract: 8 coalesced uint4 loads front-batched (MLP_p1 = 8)
    uint4 v[8];
    #pragma unroll
    for (int k = 0; k < 8; k++) v[k] = x[base + k * 256];
    #pragma unroll
    for (int k = 0; k < 8; k++) {
        if (v[k].x | v[k].y | v[k].z | v[k].w) {
            unsigned a[4] = { v[k].x, v[k].y, v[k].z, v[k].w };
            int eb = (base + k * 256) * 4;
            #pragma unroll
            for (int j = 0; j < 4; j++) {
                if (a[j] != 0u) {
                    int idx = eb + j;
                    int row = idx / V;
                    g_xidx[row] = idx - row * V;
                }
            }
        }
    }
}

// ---------------------------------------------------------------------------
// K_BC: segmap + per-batch last-block stitch/replay/scatter.
//   4 blocks per batch compute 8 segment maps each (x32-replicated table,
//   ILP-9 chains). After writing, each block fences and bumps g_done[b];
//   the 4th block re-reads the batch's segmaps, stitches the 32 entry states,
//   replays each segment and scatters the 1.0f's into the zeroed output.
//   g_done[b] is reset to 0 by the last block -> graph-replay deterministic.
// ---------------------------------------------------------------------------
extern __shared__ unsigned s_tab[];   // 514 * REP = 65792 B dynamic

__global__ void __launch_bounds__(256) k_BC(float* __restrict__ out) {
    __shared__ unsigned tabS[514];
    __shared__ __align__(16) int   sxs[UNITS * SEGLEN];  // [t*8 + u]
    __shared__ __align__(16) int   sx[L];
    __shared__ __align__(16) short smap[SEG * NST];
    __shared__ short entry[SEG];
    __shared__ int   isLast;

    int bid = blockIdx.x;
    int tid = threadIdx.x;
    int b  = bid >> 2;
    int s0 = (bid & 3) * UNITS;

    for (int i = tid; i < 514; i += 256) tabS[i] = g_tab[slot_src(i)];
    {   // sxs: u = warp, t = lane -> coalesced LDG
        int u = tid >> 5, t = tid & 31;
        sxs[t * 8 + u] = g_xidx[b * L + (s0 + u) * SEGLEN + t];
    }
    __syncthreads();
    for (int i = tid; i < 514 * REP; i += 256) s_tab[i] = tabS[i >> 5];
    __syncthreads();

    // ---- segment maps: ILP-9 dependent chains, conflict-free gathers ----
    int rep = tid & 31;
    int p4  = 256 + (tid & 1);          // leftover states 256/257 (redundant xN)
    int un8 = (tid >> 1) & 7;

    int idx[9];
    #pragma unroll
    for (int j = 0; j < 8; j++) idx[j] = tid;           // state tid -> slot tid
    idx[8] = (p4 == V) ? 513 : p4;

    #pragma unroll 4
    for (int t = 0; t < SEGLEN; t++) {
        uint4 xv0 = *(const uint4*)&sxs[t * 8];
        uint4 xv1 = *(const uint4*)&sxs[t * 8 + 4];
        unsigned xs[9] = { xv0.x, xv0.y, xv0.z, xv0.w,
                           xv1.x, xv1.y, xv1.z, xv1.w,
                           (unsigned)sxs[t * 8 + un8] };
        #pragma unroll
        for (int j = 0; j < 9; j++) {
            unsigned e = s_tab[idx[j] * REP + rep];
            unsigned z = xs[j] * (e & 0xFFFFu) + (e >> 16);
            int w = (int)(z & 255u) - (int)(z >> 8) + V;
            idx[j] = (e != 0u) ? w : 513;
        }
    }

    short* seg0 = g_segmap + (size_t)(b * SEG + s0) * NST;
    #pragma unroll
    for (int j = 0; j < 8; j++)
        seg0[j * NST + tid] = (short)slot_state(idx[j]);
    seg0[un8 * NST + p4] = (short)slot_state(idx[8]);    // redundant, same value

    // ---- publish + elect last block of this batch ----
    __threadfence();                     // make our segmap writes visible
    __syncthreads();
    if (tid == 0) {
        int old = atomicAdd(&g_done[b], 1);
        isLast = (old == 3);
    }
    __syncthreads();
    if (!isLast) return;
    __threadfence();                     // acquire: see peers' segmap writes

    // ---- last block: load batch data, stitch, replay, scatter ----
    ((uint4*)sx)[tid] = ((const uint4*)(g_xidx + b * L))[tid];
    {
        const uint4* src = (const uint4*)(g_segmap + (size_t)b * SEG * NST);
        uint4* dst = (uint4*)smap;
        #pragma unroll
        for (int k = 0; k < 4; k++) dst[tid + 256 * k] = src[tid + 256 * k];
        const int rem = (SEG * NST * 2) / 16 - 1024;     // 8
        if (tid < rem) dst[1024 + tid] = src[1024 + tid];
    }
    __syncthreads();

    if (tid == 0) {
        int st = V;   // ZERO
        #pragma unroll
        for (int s = 0; s < SEG; s++) { entry[s] = (short)st; st = smap[s * NST + st]; }
        g_done[b] = 0;                   // self-reset for next graph replay
    }
    __syncthreads();

    if (tid < SEG) {
        int s   = tid;
        int ent = entry[s];
        int ix  = (ent == V) ? 513 : ent;
        float* orow = out + (size_t)(b * L + s * SEGLEN) * V;
        #pragma unroll 8
        for (int t = 0; t < SEGLEN; t++) {
            unsigned e = tabS[ix];
            unsigned z = (unsigned)sx[s * SEGLEN + t] * (e & 0xFFFFu) + (e >> 16);
            int w = (int)(z & 255u) - (int)(z >> 8) + V;
            bool ok = (e != 0u);
            ix = ok ? w : 513;
            if (ok) {
                int oi = (w >= V) ? w - V : w;
                orow[(size_t)t * V + oi] = 1.0f;
            }
        }
    }
}

// ---------------------------------------------------------------------------
extern "C" void kernel_launch(void* const* d_in, const int* in_sizes, int n_in,
                              void* d_out, int out_size) {
    const float* x   = (const float*)d_in[0];   // [B, L, V] f32
    const float* W   = (const float*)d_in[1];   // [V, 2V]   f32
    const float* bb  = (const float*)d_in[2];   // [2V]      f32
    const int*   inv = (const int*)  d_in[3];   // [V]       i32

    const int dynsmem = 514 * REP * 4;          // 65792 B
    cudaFuncSetAttribute(k_BC, cudaFuncAttributeMaxDynamicSharedMemorySize, dynsmem);

    k_A<<<TBLK + 2 * MIXB, 256>>>(W, bb, inv, (const uint4*)x, (uint4*)d_out);
    k_BC<<<SEGBLK, 256, dynsmem>>>((float*)d_out);
}